// round 4
// baseline (speedup 1.0000x reference)
#include <cuda_runtime.h>
#include <cuda_bf16.h>

// Problem constants (fixed by the dataset builder)
#define BB    64          // batches
#define SS    4096        // spikes per batch
#define LL    25          // Lmax (interior pixel feeds 5x5 output positions)
#define NBINS 3600        // OH*OW = 60*60
#define CAPC  128         // cap
#define NC    64          // chunks per batch
#define CHUNK (SS / NC)   // 64 spikes per chunk
#define NSC   32          // superchunks (128 spikes each) for packed counting

// Scratch (static device globals — allocation-free per harness rules)
// Packed counts: for superchunk sc, low 16 bits = chunk 2sc, high 16 = chunk 2sc+1.
__device__ unsigned int   g_counts[BB * NSC * NBINS];   // 29.5 MB
__device__ unsigned short g_off[BB * NC * NBINS];       // 29.5 MB exclusive prefix

// ---------------------------------------------------------------------------
// Kernel 1: fill output with -1.0f. 29,491,200 floats = 7,372,800 float4.
// ---------------------------------------------------------------------------
__global__ void fill_kernel(float4* __restrict__ out) {
    int i = blockIdx.x * blockDim.x + threadIdx.x;
    float4 v = make_float4(-1.0f, -1.0f, -1.0f, -1.0f);
    int base = i * 4;
    out[base + 0] = v;
    out[base + 1] = v;
    out[base + 2] = v;
    out[base + 3] = v;
}

// ---------------------------------------------------------------------------
// Kernel 2: per-chunk histogram, packed. One block (128 thr) per superchunk
// of 128 spikes = 2 chunks of 64. Warps 0,1 count chunk A (+1), warps 2,3
// chunk B (+1<<16). Max 64 per half -> no carry between halves.
// ---------------------------------------------------------------------------
__global__ void count_kernel(const int* __restrict__ spikes,
                             const int* __restrict__ indices) {
    __shared__ unsigned int hist[NBINS];
    int tid = threadIdx.x;
    for (int i = tid; i < NBINS; i += 128) hist[i] = 0u;
    __syncthreads();

    int b  = blockIdx.x >> 5;   // NSC == 32
    int sc = blockIdx.x & 31;
    int warp = tid >> 5, lane = tid & 31;
    const int* sp = spikes + b * SS + sc * 128 + warp * 32;
    unsigned int add = (warp < 2) ? 1u : 65536u;

    for (int k = 0; k < 32; k++) {
        int id = __ldg(&sp[k]);                      // uniform broadcast load
        int j = -1;
        if (lane < LL) j = __ldg(&indices[id * LL + lane]);
        if (j >= 0) {
            unsigned int bin = (unsigned int)j % (unsigned int)NBINS;
            atomicAdd(&hist[bin], add);
        }
    }
    __syncthreads();

    unsigned int* dst = g_counts + (size_t)blockIdx.x * NBINS;
    for (int i = tid; i < NBINS; i += 128) dst[i] = hist[i];
}

// ---------------------------------------------------------------------------
// Kernel 3: exclusive scan over NC=64 chunks per (b,bin), reading packed
// superchunk counts. Consecutive threads = consecutive bins -> coalesced.
// ---------------------------------------------------------------------------
__global__ void scan_kernel() {
    int idx = blockIdx.x * 256 + threadIdx.x;
    if (idx >= BB * NBINS) return;
    int b = idx / NBINS;
    int bin = idx - b * NBINS;
    unsigned int sum = 0;
#pragma unroll
    for (int sc = 0; sc < NSC; sc++) {
        unsigned int v = g_counts[((size_t)(b * NSC + sc)) * NBINS + bin];
        g_off[((size_t)(b * NC + 2 * sc    )) * NBINS + bin] = (unsigned short)sum;
        sum += (v & 0xFFFFu);
        g_off[((size_t)(b * NC + 2 * sc + 1)) * NBINS + bin] = (unsigned short)sum;
        sum += (v >> 16);
    }
}

// ---------------------------------------------------------------------------
// Kernel 4: ordered scatter. One WARP per (b,chunk) of 64 spikes; 4 warps per
// block (28.8 KB smem -> 7 blocks/SM; grid 1024 ~= one full wave).
// Warp walks its spikes in groups of 4 with a depth-4 software pipeline:
// the next group's 4 indices rows are gathered (L2, ~250cyc) while the
// current 4 are processed serially (~240cyc) -> latency hidden.
// Spike ids are batch-loaded once into 2 regs/lane and shuffled out.
// Ordering: within one spike the 25 bins are distinct, so lanes never collide
// on a counter; __syncwarp between spikes orders counter RMWs across spikes.
// ---------------------------------------------------------------------------
__global__ void scatter_kernel(const int* __restrict__ spikes,
                               const int* __restrict__ indices,
                               float* __restrict__ out) {
    __shared__ unsigned short cnt[4 * NBINS];   // 28.8 KB
    const unsigned int FULL = 0xffffffffu;
    int warp = threadIdx.x >> 5, lane = threadIdx.x & 31;
    int chunk = blockIdx.x * 4 + warp;
    int b = chunk >> 6;        // NC == 64
    int c = chunk & 63;

    // Vectorized preload of counters with per-chunk base offsets.
    unsigned short* my = cnt + warp * NBINS;
    {
        const unsigned int* offu =
            (const unsigned int*)(g_off + (size_t)chunk * NBINS);
        unsigned int* myu = (unsigned int*)my;
        for (int i = lane; i < NBINS / 2; i += 32) myu[i] = __ldg(&offu[i]);
    }

    const int* sp = spikes + b * SS + c * CHUNK;
    int idlo = __ldg(&sp[lane]);        // spikes 0..31
    int idhi = __ldg(&sp[32 + lane]);   // spikes 32..63
    float* outb = out + (size_t)b * CAPC * NBINS;
    bool act = lane < LL;
    __syncwarp();

    // gather of indices row for spike s (id broadcast via shuffle)
    #define GATHER(dst, s) do {                                              \
        int _id = ((s) < 32) ? __shfl_sync(FULL, idlo, (s))                  \
                             : __shfl_sync(FULL, idhi, (s) - 32);            \
        (dst) = act ? __ldg(&indices[_id * LL + lane]) : -1;                 \
    } while (0)

    #define PROCESS(jv) do {                                                 \
        if ((jv) >= 0) {                                                     \
            unsigned int ju  = (unsigned int)(jv);                           \
            unsigned int ckk = ju / (unsigned int)NBINS;                     \
            unsigned int bin = ju - ckk * (unsigned int)NBINS;               \
            unsigned int r = my[bin];                                        \
            my[bin] = (unsigned short)(r + 1u);                              \
            if (r < CAPC) outb[(size_t)r * NBINS + bin] = (float)ckk;        \
        }                                                                    \
        __syncwarp();                                                        \
    } while (0)

    int j0, j1, j2, j3;
    GATHER(j0, 0); GATHER(j1, 1); GATHER(j2, 2); GATHER(j3, 3);

    #pragma unroll 4
    for (int g = 0; g < CHUNK / 4 - 1; g++) {
        int s = g * 4;
        int n0, n1, n2, n3;
        GATHER(n0, s + 4); GATHER(n1, s + 5);
        GATHER(n2, s + 6); GATHER(n3, s + 7);
        PROCESS(j0); PROCESS(j1); PROCESS(j2); PROCESS(j3);
        j0 = n0; j1 = n1; j2 = n2; j3 = n3;
    }
    PROCESS(j0); PROCESS(j1); PROCESS(j2); PROCESS(j3);

    #undef GATHER
    #undef PROCESS
}

// ---------------------------------------------------------------------------
extern "C" void kernel_launch(void* const* d_in, const int* in_sizes, int n_in,
                              void* d_out, int out_size) {
    const int* spikes  = (const int*)d_in[0];   // (64, 4096, 1, 1) int32
    const int* indices = (const int*)d_in[1];   // (131072, 25) int32
    float* out = (float*)d_out;                 // (64, 128, 60, 60) float32

    fill_kernel<<<7200, 256>>>((float4*)out);
    count_kernel<<<BB * NSC, 128>>>(spikes, indices);
    scan_kernel<<<(BB * NBINS + 255) / 256, 256>>>();
    scatter_kernel<<<BB * NC / 4, 128>>>(spikes, indices, out);
}

// round 5
// speedup vs baseline: 1.1941x; 1.1941x over previous
#include <cuda_runtime.h>
#include <cuda_bf16.h>

// Problem constants (fixed by the dataset builder)
#define BB    64          // batches
#define SS    4096        // spikes per batch
#define LL    25          // Lmax
#define NBINS 3600        // OH*OW
#define CAPC  128         // cap
#define NC    64          // chunks per batch
#define CHUNK (SS / NC)   // 64 spikes per chunk
#define NSC   16          // superchunks of 256 spikes (4 chunks) for packed count
#define OFFCLAMP 160u     // offsets >= 128 are dead; clamp keeps u8 exact where live

// Scratch (static device globals — allocation-free per harness rules)
// g_counts[b][sc][bin]: 4 chunks' counts in the 4 byte fields (each <= 64).
__device__ unsigned int  g_counts[BB * NSC * NBINS];          // 14.7 MB
__device__ unsigned char g_off[(size_t)BB * NC * NBINS];      // 14.7 MB, clamped u8

// ---------------------------------------------------------------------------
// Kernel 1: fill output with -1.0f (118 MB, roofline-bound).
// ---------------------------------------------------------------------------
__global__ void fill_kernel(float4* __restrict__ out) {
    int i = blockIdx.x * blockDim.x + threadIdx.x;
    float4 v = make_float4(-1.0f, -1.0f, -1.0f, -1.0f);
    int base = i * 4;
    out[base + 0] = v;
    out[base + 1] = v;
    out[base + 2] = v;
    out[base + 3] = v;
}

// ---------------------------------------------------------------------------
// Kernel 2: packed per-chunk histogram. One block (256 thr = 8 warps) per
// superchunk of 256 spikes = 4 chunks of 64. Warps 2k,2k+1 count chunk k
// into byte field k (add = 1<<(8k)). Fields never exceed 64 -> no carry.
// ---------------------------------------------------------------------------
__global__ void count_kernel(const int* __restrict__ spikes,
                             const int* __restrict__ indices) {
    __shared__ unsigned int hist[NBINS];
    int tid = threadIdx.x;
    for (int i = tid; i < NBINS; i += 256) hist[i] = 0u;
    __syncthreads();

    int b  = blockIdx.x >> 4;   // NSC == 16
    int sc = blockIdx.x & 15;
    int warp = tid >> 5, lane = tid & 31;
    const int* sp = spikes + b * SS + sc * 256 + warp * 32;
    unsigned int add = 1u << (8 * (warp >> 1));

    for (int k = 0; k < 32; k++) {
        int id = __ldg(&sp[k]);                      // uniform broadcast load
        int j = -1;
        if (lane < LL) j = __ldg(&indices[id * LL + lane]);
        if (j >= 0) {
            unsigned int bin = (unsigned int)j % (unsigned int)NBINS;
            atomicAdd(&hist[bin], add);
        }
    }
    __syncthreads();

    unsigned int* dst = g_counts + (size_t)blockIdx.x * NBINS;
    for (int i = tid; i < NBINS; i += 256) dst[i] = hist[i];
}

// ---------------------------------------------------------------------------
// Kernel 3: exclusive scan over 64 chunks per (b,bin). Reads packed byte
// counts, writes u8 offsets clamped to OFFCLAMP (dead >= 128 anyway).
// Thread per (b,bin): coalesced u32 reads, coalesced byte writes.
// ---------------------------------------------------------------------------
__global__ void scan_kernel() {
    int idx = blockIdx.x * 256 + threadIdx.x;
    if (idx >= BB * NBINS) return;
    int b = idx / NBINS;
    int bin = idx - b * NBINS;
    unsigned int sum = 0;
#pragma unroll
    for (int sc = 0; sc < NSC; sc++) {
        unsigned int v = g_counts[((size_t)(b * NSC + sc)) * NBINS + bin];
#pragma unroll
        for (int sub = 0; sub < 4; sub++) {
            int c = sc * 4 + sub;
            g_off[((size_t)(b * NC + c)) * NBINS + bin] =
                (unsigned char)min(sum, OFFCLAMP);
            sum += (v >> (8 * sub)) & 0xFFu;
        }
    }
}

// ---------------------------------------------------------------------------
// Kernel 4: ordered scatter. One WARP per (b,chunk) of 64 spikes; 4 warps per
// block, 14.4 KB smem (u8 counters). Depth-4 software pipeline: next group's
// 4 indices rows gathered while current 4 process. Counters preloaded with
// clamped base offsets; max counter value 160+64=224 < 256 so u8 is exact
// wherever it matters (r < 128 writes).
// Ordering: within one spike the 25 bins are distinct so lanes never collide;
// __syncwarp between spikes orders the byte RMWs across spikes.
// ---------------------------------------------------------------------------
__global__ void scatter_kernel(const int* __restrict__ spikes,
                               const int* __restrict__ indices,
                               float* __restrict__ out) {
    __shared__ __align__(16) unsigned char cnt[4 * NBINS];   // 14.4 KB
    const unsigned int FULL = 0xffffffffu;
    int warp = threadIdx.x >> 5, lane = threadIdx.x & 31;
    int chunk = blockIdx.x * 4 + warp;
    int b = chunk >> 6;        // NC == 64
    int c = chunk & 63;

    // uint4 preload of u8 counters (3600 B = 225 uint4 per warp).
    unsigned char* my = cnt + warp * NBINS;
    {
        const uint4* offv = (const uint4*)(g_off + (size_t)chunk * NBINS);
        uint4* myv = (uint4*)my;
        for (int i = lane; i < NBINS / 16; i += 32) myv[i] = __ldg(&offv[i]);
    }

    const int* sp = spikes + b * SS + c * CHUNK;
    int idlo = __ldg(&sp[lane]);        // spikes 0..31
    int idhi = __ldg(&sp[32 + lane]);   // spikes 32..63
    float* outb = out + (size_t)b * CAPC * NBINS;
    bool act = lane < LL;
    __syncwarp();

    #define GATHER(dst, s) do {                                              \
        int _id = ((s) < 32) ? __shfl_sync(FULL, idlo, (s))                  \
                             : __shfl_sync(FULL, idhi, (s) - 32);            \
        (dst) = act ? __ldg(&indices[_id * LL + lane]) : -1;                 \
    } while (0)

    #define PROCESS(jv) do {                                                 \
        if ((jv) >= 0) {                                                     \
            unsigned int ju  = (unsigned int)(jv);                           \
            unsigned int ckk = ju / (unsigned int)NBINS;                     \
            unsigned int bin = ju - ckk * (unsigned int)NBINS;               \
            unsigned int r = my[bin];                                        \
            my[bin] = (unsigned char)(r + 1u);                               \
            if (r < CAPC) outb[(size_t)r * NBINS + bin] = (float)ckk;        \
        }                                                                    \
        __syncwarp();                                                        \
    } while (0)

    int j0, j1, j2, j3;
    GATHER(j0, 0); GATHER(j1, 1); GATHER(j2, 2); GATHER(j3, 3);

    #pragma unroll 4
    for (int g = 0; g < CHUNK / 4 - 1; g++) {
        int s = g * 4;
        int n0, n1, n2, n3;
        GATHER(n0, s + 4); GATHER(n1, s + 5);
        GATHER(n2, s + 6); GATHER(n3, s + 7);
        PROCESS(j0); PROCESS(j1); PROCESS(j2); PROCESS(j3);
        j0 = n0; j1 = n1; j2 = n2; j3 = n3;
    }
    PROCESS(j0); PROCESS(j1); PROCESS(j2); PROCESS(j3);

    #undef GATHER
    #undef PROCESS
}

// ---------------------------------------------------------------------------
extern "C" void kernel_launch(void* const* d_in, const int* in_sizes, int n_in,
                              void* d_out, int out_size) {
    const int* spikes  = (const int*)d_in[0];   // (64, 4096, 1, 1) int32
    const int* indices = (const int*)d_in[1];   // (131072, 25) int32
    float* out = (float*)d_out;                 // (64, 128, 60, 60) float32

    fill_kernel<<<7200, 256>>>((float4*)out);
    count_kernel<<<BB * NSC, 256>>>(spikes, indices);
    scan_kernel<<<(BB * NBINS + 255) / 256, 256>>>();
    scatter_kernel<<<BB * NC / 4, 128>>>(spikes, indices, out);
}